// round 3
// baseline (speedup 1.0000x reference)
#include <cuda_runtime.h>

// InterpolateSparse2d: bilinear sampling of x[B,C,Hx,Wx] at pos[B,N,2] -> out[B,N,C]
// Shapes fixed by the problem:
#define BX 16
#define CX 64
#define HXX 240
#define WXX 320
#define NP 20000

__global__ void __launch_bounds__(256) interp_sparse2d_kernel(
    const float* __restrict__ x,    // [B, C, Hx, Wx]
    const float* __restrict__ pos,  // [B, N, 2]
    const int* __restrict__ Hp,     // scalar
    const int* __restrict__ Wp,     // scalar
    float* __restrict__ out)        // [B, N, C]
{
    const int c = threadIdx.x;                          // 0..63 (channel)
    const int p = blockIdx.x * blockDim.y + threadIdx.y; // global point id in [0, B*N)
    if (p >= BX * NP) return;

    const int b = p / NP;

    const float Wf = (float)__ldg(Wp);
    const float Hf = (float)__ldg(Hp);

    // pos load: same address across all 64 threads of the point -> broadcast
    const float px = __ldg(pos + (size_t)p * 2 + 0);
    const float py = __ldg(pos + (size_t)p * 2 + 1);

    // match reference: pos_x = pos * (Wx-1) / W
    const float posx = px * (float)(WXX - 1) / Wf;
    const float posy = py * (float)(HXX - 1) / Hf;

    int x0 = (int)floorf(posx);
    x0 = min(max(x0, 0), WXX - 1);
    const int x1 = min(x0 + 1, WXX - 1);
    int y0 = (int)floorf(posy);
    y0 = min(max(y0, 0), HXX - 1);
    const int y1 = min(y0 + 1, HXX - 1);

    const float x0f = (float)x0, x1f = (float)x1;
    const float y0f = (float)y0, y1f = (float)y1;

    const float wa = (x1f - posx) * (y1f - posy); // (x0,y0)
    const float wb = (x1f - posx) * (posy - y0f); // (x0,y1)
    const float wc = (posx - x0f) * (y1f - posy); // (x1,y0)
    const float wd = (posx - x0f) * (posy - y0f); // (x1,y1)

    const float* plane = x + ((size_t)(b * CX + c)) * (HXX * WXX);
    const float Ia = __ldg(plane + y0 * WXX + x0);
    const float Ib = __ldg(plane + y1 * WXX + x0);
    const float Ic = __ldg(plane + y0 * WXX + x1);
    const float Id = __ldg(plane + y1 * WXX + x1);

    out[(size_t)p * CX + c] = wa * Ia + wb * Ib + wc * Ic + wd * Id;
}

extern "C" void kernel_launch(void* const* d_in, const int* in_sizes, int n_in,
                              void* d_out, int out_size) {
    const float* x   = (const float*)d_in[0];
    const float* pos = (const float*)d_in[1];
    const int*   Hp  = (const int*)d_in[2];
    const int*   Wp  = (const int*)d_in[3];
    float* out = (float*)d_out;

    dim3 block(CX, 4, 1);                    // 64 channels x 4 points = 256 threads
    dim3 grid((BX * NP + 3) / 4, 1, 1);      // 80000 blocks
    interp_sparse2d_kernel<<<grid, block>>>(x, pos, Hp, Wp, out);
}

// round 5
// speedup vs baseline: 3.0291x; 3.0291x over previous
#include <cuda_runtime.h>

// InterpolateSparse2d: bilinear sampling of x[B,C,Hx,Wx] at pos[B,N,2] -> out[B,N,C]
#define BX 16
#define CX 64
#define HXX 240
#define WXX 320
#define NP 20000
#define HW (HXX * WXX)   // 76800

// 315 MB NHWC scratch: [B, Hx, Wx, C]
__device__ float g_nhwc[(size_t)BX * HW * CX];

// ---------------------------------------------------------------------------
// Kernel 1: NCHW -> NHWC transpose via shared-memory 32x32 tiles.
// For each batch b: transpose [C=64, HW=76800] -> [HW, 64].
// grid = (HW/32, C/32, B), block = (32, 8). Both GMEM sides 128B-coalesced.
// ---------------------------------------------------------------------------
__global__ void __launch_bounds__(256) nchw_to_nhwc_kernel(
    const float* __restrict__ x)
{
    __shared__ float tile[32][33];

    const int b  = blockIdx.z;
    const int c0 = blockIdx.y * 32;
    const int s0 = blockIdx.x * 32;   // hw offset

    // load 32 (c) x 32 (hw), coalesced along hw
    const float* src = x + ((size_t)b * CX + c0) * HW + s0;
    #pragma unroll
    for (int i = 0; i < 32; i += 8) {
        tile[threadIdx.y + i][threadIdx.x] =
            src[(size_t)(threadIdx.y + i) * HW + threadIdx.x];
    }
    __syncthreads();

    // store 32 (hw) x 32 (c), coalesced along c
    float* dst = g_nhwc + ((size_t)b * HW + s0) * CX + c0;
    #pragma unroll
    for (int i = 0; i < 32; i += 8) {
        dst[(size_t)(threadIdx.y + i) * CX + threadIdx.x] =
            tile[threadIdx.x][threadIdx.y + i];
    }
}

// ---------------------------------------------------------------------------
// Kernel 2: gather + bilinear blend from NHWC scratch.
// 16 threads per point, float4 = 4 channels per thread.
// block = (16, 16) -> 16 points per block; grid = B*N/16.
// ---------------------------------------------------------------------------
__global__ void __launch_bounds__(256) interp_gather_nhwc_kernel(
    const float* __restrict__ pos,  // [B, N, 2]
    const int* __restrict__ Hp,
    const int* __restrict__ Wp,
    float* __restrict__ out)        // [B, N, C]
{
    const int c4 = threadIdx.x;                            // 0..15 -> channels 4*c4..
    const int p  = blockIdx.x * blockDim.y + threadIdx.y;  // global point id
    if (p >= BX * NP) return;

    const int b = p / NP;

    const float Wf = (float)__ldg(Wp);
    const float Hf = (float)__ldg(Hp);

    const float px = __ldg(pos + (size_t)p * 2 + 0);
    const float py = __ldg(pos + (size_t)p * 2 + 1);

    const float posx = px * (float)(WXX - 1) / Wf;
    const float posy = py * (float)(HXX - 1) / Hf;

    int x0 = (int)floorf(posx);
    x0 = min(max(x0, 0), WXX - 1);
    const int x1 = min(x0 + 1, WXX - 1);
    int y0 = (int)floorf(posy);
    y0 = min(max(y0, 0), HXX - 1);
    const int y1 = min(y0 + 1, HXX - 1);

    const float x0f = (float)x0, x1f = (float)x1;
    const float y0f = (float)y0, y1f = (float)y1;

    const float wa = (x1f - posx) * (y1f - posy); // (x0,y0)
    const float wb = (x1f - posx) * (posy - y0f); // (x0,y1)
    const float wc = (posx - x0f) * (y1f - posy); // (x1,y0)
    const float wd = (posx - x0f) * (posy - y0f); // (x1,y1)

    const size_t base = (size_t)b * HW;
    const float4* pa = (const float4*)(g_nhwc + (base + (size_t)y0 * WXX + x0) * CX);
    const float4* pb = (const float4*)(g_nhwc + (base + (size_t)y1 * WXX + x0) * CX);
    const float4* pc = (const float4*)(g_nhwc + (base + (size_t)y0 * WXX + x1) * CX);
    const float4* pd = (const float4*)(g_nhwc + (base + (size_t)y1 * WXX + x1) * CX);

    const float4 Ia = __ldg(pa + c4);
    const float4 Ib = __ldg(pb + c4);
    const float4 Ic = __ldg(pc + c4);
    const float4 Id = __ldg(pd + c4);

    float4 r;
    r.x = wa * Ia.x + wb * Ib.x + wc * Ic.x + wd * Id.x;
    r.y = wa * Ia.y + wb * Ib.y + wc * Ic.y + wd * Id.y;
    r.z = wa * Ia.z + wb * Ib.z + wc * Ic.z + wd * Id.z;
    r.w = wa * Ia.w + wb * Ib.w + wc * Ic.w + wd * Id.w;

    ((float4*)(out + (size_t)p * CX))[c4] = r;
}

extern "C" void kernel_launch(void* const* d_in, const int* in_sizes, int n_in,
                              void* d_out, int out_size) {
    const float* x   = (const float*)d_in[0];
    const float* pos = (const float*)d_in[1];
    const int*   Hp  = (const int*)d_in[2];
    const int*   Wp  = (const int*)d_in[3];
    float* out = (float*)d_out;

    // Phase 1: layout transform NCHW -> NHWC
    {
        dim3 block(32, 8, 1);
        dim3 grid(HW / 32, CX / 32, BX);   // (2400, 2, 16)
        nchw_to_nhwc_kernel<<<grid, block>>>(x);
    }
    // Phase 2: coalesced gather + blend
    {
        dim3 block(16, 16, 1);             // 16 ch-quads x 16 points
        dim3 grid((BX * NP + 15) / 16, 1, 1);
        interp_gather_nhwc_kernel<<<grid, block>>>(pos, Hp, Wp, out);
    }
}

// round 8
// speedup vs baseline: 3.3324x; 1.1001x over previous
#include <cuda_runtime.h>

// InterpolateSparse2d: bilinear sampling of x[B,C,Hx,Wx] at pos[B,N,2] -> out[B,N,C]
// Chunked two-phase: per 2-batch chunk, transpose NCHW->NHWC into a REUSED
// 39.3 MB scratch (stays L2-resident), then gather from it while it's hot.
#define BX 16
#define CX 64
#define HXX 240
#define WXX 320
#define NP 20000
#define HW (HXX * WXX)     // 76800
#define CHUNK_B 2          // batches per chunk
#define NCHUNK (BX / CHUNK_B)

// Reused NHWC scratch for one chunk: [CHUNK_B, Hx, Wx, C] = 39.3 MB (fits L2)
__device__ float g_nhwc[(size_t)CHUNK_B * HW * CX];

// ---------------------------------------------------------------------------
// Kernel 1: NCHW -> NHWC transpose for one chunk.
// x reads use __ldcs (evict-first) so the x stream doesn't displace the
// scratch lines we want resident in L2.
// grid = (HW/32, C/32, CHUNK_B), block = (32, 8).
// ---------------------------------------------------------------------------
__global__ void __launch_bounds__(256) nchw_to_nhwc_chunk_kernel(
    const float* __restrict__ x_chunk)   // x + chunk*CHUNK_B*C*HW
{
    __shared__ float tile[32][33];

    const int b  = blockIdx.z;           // batch within chunk
    const int c0 = blockIdx.y * 32;
    const int s0 = blockIdx.x * 32;      // hw offset

    const float* src = x_chunk + ((size_t)b * CX + c0) * HW + s0;
    #pragma unroll
    for (int i = 0; i < 32; i += 8) {
        tile[threadIdx.y + i][threadIdx.x] =
            __ldcs(src + (size_t)(threadIdx.y + i) * HW + threadIdx.x);
    }
    __syncthreads();

    float* dst = g_nhwc + ((size_t)b * HW + s0) * CX + c0;
    #pragma unroll
    for (int i = 0; i < 32; i += 8) {
        dst[(size_t)(threadIdx.y + i) * CX + threadIdx.x] =
            tile[threadIdx.x][threadIdx.y + i];
    }
}

// ---------------------------------------------------------------------------
// Kernel 2: gather + bilinear blend from L2-hot NHWC scratch for one chunk.
// 16 threads per point, float4 = 4 channels per thread.
// out stores use __stcs (streaming) to avoid polluting L2.
// ---------------------------------------------------------------------------
__global__ void __launch_bounds__(256) interp_gather_chunk_kernel(
    const float* __restrict__ pos,   // [B, N, 2] (full tensor)
    const int* __restrict__ Hp,
    const int* __restrict__ Wp,
    float* __restrict__ out,         // [B, N, C] (full tensor)
    int point_base)                  // chunk * CHUNK_B * NP
{
    const int c4 = threadIdx.x;                                  // 0..15
    const int pl = blockIdx.x * blockDim.y + threadIdx.y;        // chunk-local point
    if (pl >= CHUNK_B * NP) return;

    const int p       = point_base + pl;   // global point id
    const int b_local = pl / NP;           // batch within chunk

    const float Wf = (float)__ldg(Wp);
    const float Hf = (float)__ldg(Hp);

    const float px = __ldg(pos + (size_t)p * 2 + 0);
    const float py = __ldg(pos + (size_t)p * 2 + 1);

    const float posx = px * (float)(WXX - 1) / Wf;
    const float posy = py * (float)(HXX - 1) / Hf;

    int x0 = (int)floorf(posx);
    x0 = min(max(x0, 0), WXX - 1);
    const int x1 = min(x0 + 1, WXX - 1);
    int y0 = (int)floorf(posy);
    y0 = min(max(y0, 0), HXX - 1);
    const int y1 = min(y0 + 1, HXX - 1);

    const float x0f = (float)x0, x1f = (float)x1;
    const float y0f = (float)y0, y1f = (float)y1;

    const float wa = (x1f - posx) * (y1f - posy); // (x0,y0)
    const float wb = (x1f - posx) * (posy - y0f); // (x0,y1)
    const float wc = (posx - x0f) * (y1f - posy); // (x1,y0)
    const float wd = (posx - x0f) * (posy - y0f); // (x1,y1)

    const size_t base = (size_t)b_local * HW;
    const float4* pa = (const float4*)(g_nhwc + (base + (size_t)y0 * WXX + x0) * CX);
    const float4* pb = (const float4*)(g_nhwc + (base + (size_t)y1 * WXX + x0) * CX);
    const float4* pc = (const float4*)(g_nhwc + (base + (size_t)y0 * WXX + x1) * CX);
    const float4* pd = (const float4*)(g_nhwc + (base + (size_t)y1 * WXX + x1) * CX);

    const float4 Ia = __ldg(pa + c4);
    const float4 Ib = __ldg(pb + c4);
    const float4 Ic = __ldg(pc + c4);
    const float4 Id = __ldg(pd + c4);

    float4 r;
    r.x = wa * Ia.x + wb * Ib.x + wc * Ic.x + wd * Id.x;
    r.y = wa * Ia.y + wb * Ib.y + wc * Ic.y + wd * Id.y;
    r.z = wa * Ia.z + wb * Ib.z + wc * Ic.z + wd * Id.z;
    r.w = wa * Ia.w + wb * Ib.w + wc * Ic.w + wd * Id.w;

    __stcs((float4*)(out + (size_t)p * CX) + c4, r);
}

extern "C" void kernel_launch(void* const* d_in, const int* in_sizes, int n_in,
                              void* d_out, int out_size) {
    const float* x   = (const float*)d_in[0];
    const float* pos = (const float*)d_in[1];
    const int*   Hp  = (const int*)d_in[2];
    const int*   Wp  = (const int*)d_in[3];
    float* out = (float*)d_out;

    dim3 tblock(32, 8, 1);
    dim3 tgrid(HW / 32, CX / 32, CHUNK_B);        // (2400, 2, 2)

    dim3 gblock(16, 16, 1);                       // 16 ch-quads x 16 points
    dim3 ggrid((CHUNK_B * NP + 15) / 16, 1, 1);   // 2500 blocks

    for (int chunk = 0; chunk < NCHUNK; chunk++) {
        const float* x_chunk = x + (size_t)chunk * CHUNK_B * CX * HW;
        nchw_to_nhwc_chunk_kernel<<<tgrid, tblock>>>(x_chunk);
        interp_gather_chunk_kernel<<<ggrid, gblock>>>(
            pos, Hp, Wp, out, chunk * CHUNK_B * NP);
    }
}